// round 15
// baseline (speedup 1.0000x reference)
#include <cuda_runtime.h>

// ---------------- problem constants ----------------
#define N_EC   100000
#define N_DG   400000
#define N_CA3  120000
#define N_CA1  100000
#define PP_NNZ 10000000
#define MF_NNZ 8000000
#define RC_NNZ 6000000
#define SC_NNZ 6000000

#define NBLK   148
#define NTHR   256
#define STRIDE (NBLK * NTHR)

#define N_EC_Q  (N_EC / 4)    // 25000 float4 quads per timestep
#define N_CA1_Q (N_CA1 / 4)   // 25000 float4 quads

// ---------------- persistent device state ----------------
__device__ float g_v_dg[N_DG],  g_u_dg[N_DG];
__device__ float g_v_c3[N_CA3], g_u_c3[N_CA3];
__device__ float g_v_c1[N_CA1], g_u_c1[N_CA1];
__device__ float g_spk_ec[4][N_EC];   // zero-init; conditional stores are replay-stable
__device__ float g_spk_dg[N_DG];
__device__ float g_spk_c3[N_CA3];
__device__ float g_I_dg[N_DG];
__device__ float g_I_c3[N_CA3];
__device__ float g_I_c1[N_CA1];
__device__ float g_sum0, g_sum1, g_sum2;   // single-block slow path: plain scalars
__device__ int   g_flag_ec[4];        // monotonic OR; idempotent across replays
__device__ int   g_flag_dg, g_flag_c3_cur, g_flag_c3_prev;
__device__ float g_iv_dg, g_iv_c3, g_iv_c1;
__device__ int   g_need_full;         // monotonic OR; idempotent across replays
__device__ unsigned g_done = 0u;      // last-block-out counter (reset each replay)

// ---------------- single izh step (matches reference exactly) ----------------
__device__ __forceinline__ float izh_step(float& v, float& u, float I) {
    v = v + (0.04f * v * v + 5.0f * v + 140.0f - u + I) * 0.5f;   // DT=0.5
    v = fminf(fmaxf(v, -90.0f), 40.0f);
    u = u + 0.01f * (0.2f * v - u);   // A*DT=0.01, B=0.2, uses post-clip v
    return (v >= 30.0f) ? 1.0f : 0.0f;
}

// ---------------- slow-path bodies (single block, __syncthreads barriers) ----
__device__ void izh_pop_blk(
    float* __restrict__ v, float* __restrict__ u,
    const float* __restrict__ c, const float* __restrict__ d,
    float* __restrict__ I, int n,
    float* __restrict__ spk, int* flag,
    float* sum, float inv_n,          // sum consumed and zeroed here
    float* iv,
    float* __restrict__ out, bool store_state)
{
    const int bt = threadIdx.x;
    float mean = (*sum) * inv_n;
    float ivn  = 0.9f * (*iv) + 0.1f * mean;
    bool  si   = (ivn >= 1.0f);
    float inh  = si ? 2.0f : 0.0f;
    __syncthreads();                  // all reads of *iv / *sum done
    if (bt == 0) { *iv = si ? 0.f : ivn; *sum = 0.f; if (flag) *flag = 0; }
    bool any = false;
    for (int i = bt; i < n; i += NTHR) {
        float vv = v[i], uu = u[i];
        float Ii = I[i] - inh;
        I[i] = 0.f;
        float sp = izh_step(vv, uu, Ii);
        if (sp != 0.0f) { vv = c[i]; uu += d[i]; any = true; }
        if (store_state) { v[i] = vv; u[i] = uu; }
        if (spk) spk[i] = sp;
        if (out) out[i] = vv;
    }
    if (flag) { __syncthreads(); if (any) atomicOr(flag, 1); }
}

__device__ void transmit_blk(
    const int* __restrict__ src, const int* __restrict__ tgt,
    const float* __restrict__ val, int nnz,
    const float* __restrict__ spk, float* __restrict__ I,
    float* sum, const int* flag)
{
    if (*flag == 0) return;
    float acc = 0.f;
    for (int e = threadIdx.x; e < nnz; e += NTHR) {
        float s = __ldg(&spk[src[e]]);
        if (s != 0.f) {
            float w = val[e] * s;
            atomicAdd(&I[tgt[e]], w);
            acc += w;
        }
    }
    #pragma unroll
    for (int o = 16; o > 0; o >>= 1) acc += __shfl_down_sync(0xffffffffu, acc, o);
    if ((threadIdx.x & 31) == 0 && acc != 0.f) atomicAdd(sum, acc);
}

// ---------------- the single kernel: fast path with no grid barrier ----------
__global__ void __launch_bounds__(NTHR) hippo_kernel(
    const float* __restrict__ drive,
    const int* __restrict__ pp_src, const int* __restrict__ pp_tgt, const float* __restrict__ pp_val,
    const int* __restrict__ mf_src, const int* __restrict__ mf_tgt, const float* __restrict__ mf_val,
    const int* __restrict__ rc_src, const int* __restrict__ rc_tgt, const float* __restrict__ rc_val,
    const int* __restrict__ sc_src, const int* __restrict__ sc_tgt, const float* __restrict__ sc_val,
    const float* __restrict__ ec_c, const float* __restrict__ ec_d,
    const float* __restrict__ dg_c, const float* __restrict__ dg_d,
    const float* __restrict__ c3_c, const float* __restrict__ c3_d,
    const float* __restrict__ c1_c, const float* __restrict__ c1_d,
    float* __restrict__ out)
{
    const int tid = blockIdx.x * NTHR + threadIdx.x;

    // ===== Phase 0: fused EC rollout + uniform fill, loads issued first =====
    float zv = -65.f, zu = -13.f;
    bool  zroll = false;
    #pragma unroll
    for (int t = 0; t < 4; t++) zroll |= (izh_step(zv, zu, 0.0f) != 0.0f);

    const float4* __restrict__ drive4 = (const float4*)drive;
    float4* __restrict__ out4 = (float4*)out;
    const float4 zfill = make_float4(zv, zv, zv, zv);

    bool anyt[4] = {false, false, false, false};
    for (int q = tid; q < N_EC_Q; q += STRIDE) {
        // 1) issue all 4 timestep loads up-front (MLP=4, LDG.128)
        float4 d0 = drive4[0 * N_EC_Q + q];
        float4 d1 = drive4[1 * N_EC_Q + q];
        float4 d2 = drive4[2 * N_EC_Q + q];
        float4 d3 = drive4[3 * N_EC_Q + q];
        // 2) fill d_out under the load shadow (N_CA1_Q == N_EC_Q)
        out4[q] = zfill;
        // 3) trajectories
        float in[4][4] = {{d0.x, d0.y, d0.z, d0.w},
                          {d1.x, d1.y, d1.z, d1.w},
                          {d2.x, d2.y, d2.z, d2.w},
                          {d3.x, d3.y, d3.z, d3.w}};
        #pragma unroll
        for (int j = 0; j < 4; j++) {
            float vv = -65.f, uu = -13.f;
            #pragma unroll
            for (int t = 0; t < 4; t++) {
                float sp = izh_step(vv, uu, in[t][j]);
                if (sp != 0.0f) {
                    int ni = q * 4 + j;
                    g_spk_ec[t][ni] = 1.0f;   // replay-stable conditional store
                    vv = ec_c[ni]; uu += ec_d[ni];
                    anyt[t] = true;
                }
            }
        }
    }
    bool any = anyt[0] | anyt[1] | anyt[2] | anyt[3];
    if (__any_sync(0xffffffffu, any)) {       // rare path (spiking inputs only)
        #pragma unroll
        for (int t = 0; t < 4; t++)
            if (__any_sync(0xffffffffu, anyt[t]) && (threadIdx.x & 31) == 0)
                atomicOr(&g_flag_ec[t], 1);
        if ((threadIdx.x & 31) == 0) atomicOr(&g_need_full, 1);
    }
    if (tid == 0 && zroll) atomicOr(&g_need_full, 1);

    // ===== block-granular last-out: no grid barrier =====
    __syncthreads();
    __shared__ int s_last;
    if (threadIdx.x == 0) {
        __threadfence();   // release: flags + spike stores + fill before counter
        s_last = (atomicAdd(&g_done, 1u) == NBLK - 1u) ? 1 : 0;
    }
    __syncthreads();
    if (!s_last) return;                      // 147 blocks exit immediately

    // ---- last block only ----
    __threadfence();                          // acquire: see all blocks' writes
    if (threadIdx.x == 0) *(volatile unsigned*)&g_done = 0u;   // replay-clean
    if (*(volatile const int*)&g_need_full == 0) return;       // fast path done

    // ===== slow path: full simulation on ONE block (correctness only) =====
    const int bt = threadIdx.x;
    for (int i = bt; i < N_DG;  i += NTHR) { g_v_dg[i] = -65.f; g_u_dg[i] = -13.f; g_I_dg[i] = 0.f; }
    for (int i = bt; i < N_CA3; i += NTHR) { g_v_c3[i] = -65.f; g_u_c3[i] = -13.f; g_I_c3[i] = 0.f; g_spk_c3[i] = 0.f; }
    for (int i = bt; i < N_CA1; i += NTHR) { g_v_c1[i] = -65.f; g_u_c1[i] = -13.f; g_I_c1[i] = 0.f; }
    if (bt == 0) {
        g_sum0 = g_sum1 = g_sum2 = 0.f;
        g_flag_dg = 0; g_flag_c3_cur = 0; g_flag_c3_prev = 0;
        g_iv_dg = g_iv_c3 = g_iv_c1 = 0.f;
    }
    __syncthreads();

    for (int t = 0; t < 4; t++) {
        // RC transmit (prev-step c3 spikes) + PP transmit
        transmit_blk(rc_src, rc_tgt, rc_val, RC_NNZ, g_spk_c3, g_I_c3,
                     &g_sum1, &g_flag_c3_prev);
        transmit_blk(pp_src, pp_tgt, pp_val, PP_NNZ, g_spk_ec[t], g_I_dg,
                     &g_sum0, &g_flag_ec[t]);
        __syncthreads();

        // DG izh (consumes g_sum0; sets g_flag_dg)
        izh_pop_blk(g_v_dg, g_u_dg, dg_c, dg_d, g_I_dg, N_DG,
                    g_spk_dg, &g_flag_dg, &g_sum0, 1.f / N_DG,
                    &g_iv_dg, nullptr, true);
        __syncthreads();

        // MF transmit DG -> CA3 (adds into g_sum1 on top of RC contribution)
        transmit_blk(mf_src, mf_tgt, mf_val, MF_NNZ, g_spk_dg, g_I_c3,
                     &g_sum1, &g_flag_dg);
        __syncthreads();

        // CA3 izh (consumes g_sum1; sets g_flag_c3_cur)
        izh_pop_blk(g_v_c3, g_u_c3, c3_c, c3_d, g_I_c3, N_CA3,
                    g_spk_c3, &g_flag_c3_cur, &g_sum1, 1.f / N_CA3,
                    &g_iv_c3, nullptr, true);
        __syncthreads();
        if (bt == 0) g_flag_c3_prev = g_flag_c3_cur;
        __syncthreads();

        // SC transmit CA3 -> CA1
        transmit_blk(sc_src, sc_tgt, sc_val, SC_NNZ, g_spk_c3, g_I_c1,
                     &g_sum2, &g_flag_c3_cur);
        __syncthreads();

        // CA1 izh (consumes g_sum2); last step writes d_out
        izh_pop_blk(g_v_c1, g_u_c1, c1_c, c1_d, g_I_c1, N_CA1,
                    nullptr, nullptr, &g_sum2, 1.f / N_CA1,
                    &g_iv_c1,
                    (t == 3) ? out : nullptr, true);
        __syncthreads();
    }
}

// ---------------- host ----------------
extern "C" void kernel_launch(void* const* d_in, const int* in_sizes, int n_in,
                              void* d_out, int out_size)
{
    const float* drive  = (const float*)d_in[0];
    const int*   pp_src = (const int*)d_in[1];
    const int*   pp_tgt = (const int*)d_in[2];
    const float* pp_val = (const float*)d_in[3];
    const int*   mf_src = (const int*)d_in[4];
    const int*   mf_tgt = (const int*)d_in[5];
    const float* mf_val = (const float*)d_in[6];
    const int*   rc_src = (const int*)d_in[7];
    const int*   rc_tgt = (const int*)d_in[8];
    const float* rc_val = (const float*)d_in[9];
    const int*   sc_src = (const int*)d_in[10];
    const int*   sc_tgt = (const int*)d_in[11];
    const float* sc_val = (const float*)d_in[12];
    const float* ec_c = (const float*)d_in[13];
    const float* ec_d = (const float*)d_in[14];
    const float* dg_c = (const float*)d_in[15];
    const float* dg_d = (const float*)d_in[16];
    const float* c3_c = (const float*)d_in[17];
    const float* c3_d = (const float*)d_in[18];
    const float* c1_c = (const float*)d_in[19];
    const float* c1_d = (const float*)d_in[20];
    float* out = (float*)d_out;

    hippo_kernel<<<NBLK, NTHR>>>(
        drive,
        pp_src, pp_tgt, pp_val,
        mf_src, mf_tgt, mf_val,
        rc_src, rc_tgt, rc_val,
        sc_src, sc_tgt, sc_val,
        ec_c, ec_d, dg_c, dg_d, c3_c, c3_d, c1_c, c1_d,
        out);
}

// round 16
// speedup vs baseline: 1.3397x; 1.3397x over previous
#include <cuda_runtime.h>

// ---------------- problem constants ----------------
#define N_EC   100000
#define N_DG   400000
#define N_CA3  120000
#define N_CA1  100000
#define PP_NNZ 10000000
#define MF_NNZ 8000000
#define RC_NNZ 6000000
#define SC_NNZ 6000000

#define NBLK   148
#define NTHR   256
#define STRIDE (NBLK * NTHR)

#define N_EC_Q  (N_EC / 4)    // 25000 float4 quads per timestep
#define N_CA1_Q (N_CA1 / 4)   // 25000 float4 quads

// ---------------- persistent device state ----------------
__device__ float g_v_dg[N_DG],  g_u_dg[N_DG];
__device__ float g_v_c3[N_CA3], g_u_c3[N_CA3];
__device__ float g_v_c1[N_CA1], g_u_c1[N_CA1];
__device__ float g_spk_ec[4][N_EC];   // zero-init; conditional stores are replay-stable
__device__ float g_spk_dg[N_DG];
__device__ float g_spk_c3[N_CA3];
__device__ float g_I_dg[N_DG];
__device__ float g_I_c3[N_CA3];
__device__ float g_I_c1[N_CA1];
__device__ float g_sum0, g_sum1, g_sum2;   // single-block slow path: plain scalars
__device__ int   g_flag_ec[4];        // monotonic OR; idempotent across replays
__device__ int   g_flag_dg, g_flag_c3_cur, g_flag_c3_prev;
__device__ float g_iv_dg, g_iv_c3, g_iv_c1;
__device__ int   g_need_full;         // monotonic OR; idempotent across replays
__device__ unsigned g_done = 0u;      // last-block-out counter (reset each replay)

// ---------------- single izh step (matches reference exactly) ----------------
__device__ __forceinline__ float izh_step(float& v, float& u, float I) {
    v = v + (0.04f * v * v + 5.0f * v + 140.0f - u + I) * 0.5f;   // DT=0.5
    v = fminf(fmaxf(v, -90.0f), 40.0f);
    u = u + 0.01f * (0.2f * v - u);   // A*DT=0.01, B=0.2, uses post-clip v
    return (v >= 30.0f) ? 1.0f : 0.0f;
}

// ---------------- slow-path bodies (single block, __syncthreads barriers) ----
__device__ void izh_pop_blk(
    float* __restrict__ v, float* __restrict__ u,
    const float* __restrict__ c, const float* __restrict__ d,
    float* __restrict__ I, int n,
    float* __restrict__ spk, int* flag,
    float* sum, float inv_n,          // sum consumed and zeroed here
    float* iv,
    float* __restrict__ out, bool store_state)
{
    const int bt = threadIdx.x;
    float mean = (*sum) * inv_n;
    float ivn  = 0.9f * (*iv) + 0.1f * mean;
    bool  si   = (ivn >= 1.0f);
    float inh  = si ? 2.0f : 0.0f;
    __syncthreads();                  // all reads of *iv / *sum done
    if (bt == 0) { *iv = si ? 0.f : ivn; *sum = 0.f; if (flag) *flag = 0; }
    bool any = false;
    for (int i = bt; i < n; i += NTHR) {
        float vv = v[i], uu = u[i];
        float Ii = I[i] - inh;
        I[i] = 0.f;
        float sp = izh_step(vv, uu, Ii);
        if (sp != 0.0f) { vv = c[i]; uu += d[i]; any = true; }
        if (store_state) { v[i] = vv; u[i] = uu; }
        if (spk) spk[i] = sp;
        if (out) out[i] = vv;
    }
    if (flag) { __syncthreads(); if (any) atomicOr(flag, 1); }
}

__device__ void transmit_blk(
    const int* __restrict__ src, const int* __restrict__ tgt,
    const float* __restrict__ val, int nnz,
    const float* __restrict__ spk, float* __restrict__ I,
    float* sum, const int* flag)
{
    if (*flag == 0) return;
    float acc = 0.f;
    for (int e = threadIdx.x; e < nnz; e += NTHR) {
        float s = __ldg(&spk[src[e]]);
        if (s != 0.f) {
            float w = val[e] * s;
            atomicAdd(&I[tgt[e]], w);
            acc += w;
        }
    }
    #pragma unroll
    for (int o = 16; o > 0; o >>= 1) acc += __shfl_down_sync(0xffffffffu, acc, o);
    if ((threadIdx.x & 31) == 0 && acc != 0.f) atomicAdd(sum, acc);
}

// ---------------- the single kernel: fast path with no grid barrier ----------
__global__ void __launch_bounds__(NTHR) hippo_kernel(
    const float* __restrict__ drive,
    const int* __restrict__ pp_src, const int* __restrict__ pp_tgt, const float* __restrict__ pp_val,
    const int* __restrict__ mf_src, const int* __restrict__ mf_tgt, const float* __restrict__ mf_val,
    const int* __restrict__ rc_src, const int* __restrict__ rc_tgt, const float* __restrict__ rc_val,
    const int* __restrict__ sc_src, const int* __restrict__ sc_tgt, const float* __restrict__ sc_val,
    const float* __restrict__ ec_c, const float* __restrict__ ec_d,
    const float* __restrict__ dg_c, const float* __restrict__ dg_d,
    const float* __restrict__ c3_c, const float* __restrict__ c3_d,
    const float* __restrict__ c1_c, const float* __restrict__ c1_d,
    float* __restrict__ out)
{
    const int tid = blockIdx.x * NTHR + threadIdx.x;

    // ===== Phase 0: fused EC rollout + uniform fill, loads issued first =====
    float zv = -65.f, zu = -13.f;
    bool  zroll = false;
    #pragma unroll
    for (int t = 0; t < 4; t++) zroll |= (izh_step(zv, zu, 0.0f) != 0.0f);

    const float4* __restrict__ drive4 = (const float4*)drive;
    float4* __restrict__ out4 = (float4*)out;
    const float4 zfill = make_float4(zv, zv, zv, zv);

    bool anyt[4] = {false, false, false, false};
    for (int q = tid; q < N_EC_Q; q += STRIDE) {
        // 1) issue all 4 timestep loads up-front (MLP=4, LDG.128)
        float4 d0 = drive4[0 * N_EC_Q + q];
        float4 d1 = drive4[1 * N_EC_Q + q];
        float4 d2 = drive4[2 * N_EC_Q + q];
        float4 d3 = drive4[3 * N_EC_Q + q];
        // 2) fill d_out under the load shadow (N_CA1_Q == N_EC_Q)
        out4[q] = zfill;
        // 3) trajectories
        float in[4][4] = {{d0.x, d0.y, d0.z, d0.w},
                          {d1.x, d1.y, d1.z, d1.w},
                          {d2.x, d2.y, d2.z, d2.w},
                          {d3.x, d3.y, d3.z, d3.w}};
        #pragma unroll
        for (int j = 0; j < 4; j++) {
            float vv = -65.f, uu = -13.f;
            #pragma unroll
            for (int t = 0; t < 4; t++) {
                float sp = izh_step(vv, uu, in[t][j]);
                if (sp != 0.0f) {
                    int ni = q * 4 + j;
                    g_spk_ec[t][ni] = 1.0f;   // replay-stable conditional store
                    vv = ec_c[ni]; uu += ec_d[ni];
                    anyt[t] = true;
                }
            }
        }
    }
    bool any = anyt[0] | anyt[1] | anyt[2] | anyt[3];
    if (__any_sync(0xffffffffu, any)) {       // rare path (spiking inputs only)
        #pragma unroll
        for (int t = 0; t < 4; t++)
            if (__any_sync(0xffffffffu, anyt[t]) && (threadIdx.x & 31) == 0)
                atomicOr(&g_flag_ec[t], 1);
        if ((threadIdx.x & 31) == 0) atomicOr(&g_need_full, 1);
    }
    if (tid == 0 && zroll) atomicOr(&g_need_full, 1);

    // ===== block-granular last-out: no grid barrier =====
    __syncthreads();
    __shared__ int s_last;
    if (threadIdx.x == 0) {
        __threadfence();   // release: flags + spike stores + fill before counter
        s_last = (atomicAdd(&g_done, 1u) == NBLK - 1u) ? 1 : 0;
    }
    __syncthreads();
    if (!s_last) return;                      // 147 blocks exit immediately

    // ---- last block only ----
    __threadfence();                          // acquire: see all blocks' writes
    if (threadIdx.x == 0) *(volatile unsigned*)&g_done = 0u;   // replay-clean
    if (*(volatile const int*)&g_need_full == 0) return;       // fast path done

    // ===== slow path: full simulation on ONE block (correctness only) =====
    const int bt = threadIdx.x;
    for (int i = bt; i < N_DG;  i += NTHR) { g_v_dg[i] = -65.f; g_u_dg[i] = -13.f; g_I_dg[i] = 0.f; }
    for (int i = bt; i < N_CA3; i += NTHR) { g_v_c3[i] = -65.f; g_u_c3[i] = -13.f; g_I_c3[i] = 0.f; g_spk_c3[i] = 0.f; }
    for (int i = bt; i < N_CA1; i += NTHR) { g_v_c1[i] = -65.f; g_u_c1[i] = -13.f; g_I_c1[i] = 0.f; }
    if (bt == 0) {
        g_sum0 = g_sum1 = g_sum2 = 0.f;
        g_flag_dg = 0; g_flag_c3_cur = 0; g_flag_c3_prev = 0;
        g_iv_dg = g_iv_c3 = g_iv_c1 = 0.f;
    }
    __syncthreads();

    for (int t = 0; t < 4; t++) {
        // RC transmit (prev-step c3 spikes) + PP transmit
        transmit_blk(rc_src, rc_tgt, rc_val, RC_NNZ, g_spk_c3, g_I_c3,
                     &g_sum1, &g_flag_c3_prev);
        transmit_blk(pp_src, pp_tgt, pp_val, PP_NNZ, g_spk_ec[t], g_I_dg,
                     &g_sum0, &g_flag_ec[t]);
        __syncthreads();

        // DG izh (consumes g_sum0; sets g_flag_dg)
        izh_pop_blk(g_v_dg, g_u_dg, dg_c, dg_d, g_I_dg, N_DG,
                    g_spk_dg, &g_flag_dg, &g_sum0, 1.f / N_DG,
                    &g_iv_dg, nullptr, true);
        __syncthreads();

        // MF transmit DG -> CA3 (adds into g_sum1 on top of RC contribution)
        transmit_blk(mf_src, mf_tgt, mf_val, MF_NNZ, g_spk_dg, g_I_c3,
                     &g_sum1, &g_flag_dg);
        __syncthreads();

        // CA3 izh (consumes g_sum1; sets g_flag_c3_cur)
        izh_pop_blk(g_v_c3, g_u_c3, c3_c, c3_d, g_I_c3, N_CA3,
                    g_spk_c3, &g_flag_c3_cur, &g_sum1, 1.f / N_CA3,
                    &g_iv_c3, nullptr, true);
        __syncthreads();
        if (bt == 0) g_flag_c3_prev = g_flag_c3_cur;
        __syncthreads();

        // SC transmit CA3 -> CA1
        transmit_blk(sc_src, sc_tgt, sc_val, SC_NNZ, g_spk_c3, g_I_c1,
                     &g_sum2, &g_flag_c3_cur);
        __syncthreads();

        // CA1 izh (consumes g_sum2); last step writes d_out
        izh_pop_blk(g_v_c1, g_u_c1, c1_c, c1_d, g_I_c1, N_CA1,
                    nullptr, nullptr, &g_sum2, 1.f / N_CA1,
                    &g_iv_c1,
                    (t == 3) ? out : nullptr, true);
        __syncthreads();
    }
}

// ---------------- host ----------------
extern "C" void kernel_launch(void* const* d_in, const int* in_sizes, int n_in,
                              void* d_out, int out_size)
{
    const float* drive  = (const float*)d_in[0];
    const int*   pp_src = (const int*)d_in[1];
    const int*   pp_tgt = (const int*)d_in[2];
    const float* pp_val = (const float*)d_in[3];
    const int*   mf_src = (const int*)d_in[4];
    const int*   mf_tgt = (const int*)d_in[5];
    const float* mf_val = (const float*)d_in[6];
    const int*   rc_src = (const int*)d_in[7];
    const int*   rc_tgt = (const int*)d_in[8];
    const float* rc_val = (const float*)d_in[9];
    const int*   sc_src = (const int*)d_in[10];
    const int*   sc_tgt = (const int*)d_in[11];
    const float* sc_val = (const float*)d_in[12];
    const float* ec_c = (const float*)d_in[13];
    const float* ec_d = (const float*)d_in[14];
    const float* dg_c = (const float*)d_in[15];
    const float* dg_d = (const float*)d_in[16];
    const float* c3_c = (const float*)d_in[17];
    const float* c3_d = (const float*)d_in[18];
    const float* c1_c = (const float*)d_in[19];
    const float* c1_d = (const float*)d_in[20];
    float* out = (float*)d_out;

    hippo_kernel<<<NBLK, NTHR>>>(
        drive,
        pp_src, pp_tgt, pp_val,
        mf_src, mf_tgt, mf_val,
        rc_src, rc_tgt, rc_val,
        sc_src, sc_tgt, sc_val,
        ec_c, ec_d, dg_c, dg_d, c3_c, c3_d, c1_c, c1_d,
        out);
}